// round 5
// baseline (speedup 1.0000x reference)
#include <cuda_runtime.h>
#include <cuda_bf16.h>

// ---------------------------------------------------------------------------
// SphericalIoULoss: mean(1 - sph_iou(preds, targets)) over N rows of 5 f32.
//
// Math (exact transforms, validated rel_err=1.2e-7):
//   area(a,b) = 4*acos(clip(-sin(a/2)sin(b/2),-1,1)) - 2*pi = 4*asin(sin(a/2)sin(b/2))
//   All trig args bounded -> FMA-only polynomials, no MUFU; 1 RCP per 4 rows.
//
// Memory (this round's change): smem staging tile. Global loads are fully
// coalesced float4 (4 L1 wavefronts/LDG instead of 20 for the old 80B-strided
// pattern). Smem uses a pad-21 floats/group layout: both the scatter-store
// pattern and the stride-21 compute reads are bank-conflict-free
// (gcd(21,32)=1; store addrs 21*(L/5)+4*(L%5)+c proven distinct mod 32).
//
// Single launch: block double-atomics + last-block-done finalize; the
// finalizing block resets state so graph replays start clean.
// ---------------------------------------------------------------------------

#define THREADS 256
#define TILE_G  256            // groups (of 4 rows) per tile == threads
#define PAD     21             // floats per group in smem (20 data + 1 pad)

__device__ double g_acc = 0.0;
__device__ unsigned int g_count = 0;

// sin(x), x in [0, ~0.55]; |err| ~ 1e-8
__device__ __forceinline__ float sin_s(float x) {
    float x2 = x * x;
    float t = fmaf(x2, -1.98412698e-4f, 8.33333333e-3f);
    t = fmaf(x2, t, -1.66666667e-1f);
    t = fmaf(x2, t, 1.0f);
    return x * t;
}

// asin(x), x in [0, ~0.27]; |err| ~ 1.5e-7
__device__ __forceinline__ float asin_s(float x) {
    float x2 = x * x;
    float t = fmaf(x2, 4.46428571e-2f, 7.50000000e-2f);
    t = fmaf(x2, t, 1.66666667e-1f);
    t = fmaf(x2, t, 1.0f);
    return x * t;
}

// cos(x), |x| <= pi/2; |err| ~ 5e-7
__device__ __forceinline__ float cos_m(float x) {
    float x2 = x * x;
    float t = fmaf(x2, -2.75573192e-7f, 2.48015873e-5f);
    t = fmaf(x2, t, -1.38888889e-3f);
    t = fmaf(x2, t, 4.16666667e-2f);
    t = fmaf(x2, t, -0.5f);
    t = fmaf(x2, t, 1.0f);
    return t;
}

__device__ __forceinline__ void row_iu(float t1, float p1, float a1, float b1,
                                       float t2, float p2, float a2, float b2,
                                       float& inter, float& uni) {
    float ha1 = 0.5f * a1, hb1 = 0.5f * b1;
    float ha2 = 0.5f * a2, hb2 = 0.5f * b2;
    float area1 = 4.0f * asin_s(sin_s(ha1) * sin_s(hb1));
    float area2 = 4.0f * asin_s(sin_s(ha2) * sin_s(hb2));
    float dfx = (t2 - t1) * cos_m(0.5f * (p1 + p2));
    float dfy = p2 - p1;
    float iw = fminf(ha1, dfx + ha2) - fmaxf(-ha1, dfx - ha2);
    iw = fmaxf(iw, 0.0f);
    float ih = fminf(hb1, dfy + hb2) - fmaxf(-hb1, dfy - hb2);
    ih = fmaxf(ih, 0.0f);
    inter = 4.0f * asin_s(sin_s(0.5f * iw) * sin_s(0.5f * ih));
    uni = fmaxf(area1 + area2 - inter, 1e-8f);
}

// Scatter one float4 (tile-linear float4 index f4i) into padded smem.
// floats f = 4*f4i + c; group g = f/20; lane j = f%20 (j is a multiple of 4,
// <=16, so a float4 never crosses a group boundary).
__device__ __forceinline__ void scatter4(float* __restrict__ sm, int f4i, float4 v) {
    int f = f4i * 4;
    int g = f / 20;
    int j = f - g * 20;
    float* p = sm + g * PAD + j;
    p[0] = v.x; p[1] = v.y; p[2] = v.z; p[3] = v.w;
}

__global__ __launch_bounds__(THREADS)
void k_main(const float* __restrict__ preds,
            const float* __restrict__ targets,
            int n_groups,
            int n_rows,
            float* __restrict__ out) {
    __shared__ float smP[TILE_G * PAD];
    __shared__ float smQ[TILE_G * PAD];

    int n_tiles = (n_groups + TILE_G - 1) / TILE_G;
    float loss = 0.0f;

    for (int t = blockIdx.x; t < n_tiles; t += gridDim.x) {
        long base_g = (long)t * TILE_G;
        int gcount = n_groups - base_g < TILE_G ? (int)(n_groups - base_g) : TILE_G;
        int n_f4 = gcount * 5;

        const float4* P = reinterpret_cast<const float4*>(preds) + base_g * 5;
        const float4* Q = reinterpret_cast<const float4*>(targets) + base_g * 5;

        __syncthreads();   // previous tile's compute reads must finish
#pragma unroll
        for (int k = 0; k < 5; k++) {
            int idx = threadIdx.x + THREADS * k;
            if (idx < n_f4) {
                scatter4(smP, idx, P[idx]);
                scatter4(smQ, idx, Q[idx]);
            }
        }
        __syncthreads();

        if ((int)threadIdx.x < gcount) {
            const float* pv = smP + threadIdx.x * PAD;
            const float* qv = smQ + threadIdx.x * PAD;
            float inter[4], uni[4];
#pragma unroll
            for (int r = 0; r < 4; r++) {
                row_iu(pv[5 * r + 0], pv[5 * r + 1], pv[5 * r + 2], pv[5 * r + 3],
                       qv[5 * r + 0], qv[5 * r + 1], qv[5 * r + 2], qv[5 * r + 3],
                       inter[r], uni[r]);
            }
            // one reciprocal for 4 divisions
            float u01 = uni[0] * uni[1];
            float u23 = uni[2] * uni[3];
            float r_all = 1.0f / (u01 * u23);
            float r01 = r_all * u23;
            float r23 = r_all * u01;
            loss += 4.0f - (inter[0] * (r01 * uni[1]) + inter[1] * (r01 * uni[0]) +
                            inter[2] * (r23 * uni[3]) + inter[3] * (r23 * uni[2]));
        }
    }

    // scalar tail rows (none when n_rows % 4 == 0)
    long tail_start = (long)n_groups * 4;
    if (blockIdx.x == 0 && threadIdx.x == 0) {
        for (long r = tail_start; r < (long)n_rows; r++) {
            float in_, un;
            row_iu(preds[5 * r + 0], preds[5 * r + 1], preds[5 * r + 2], preds[5 * r + 3],
                   targets[5 * r + 0], targets[5 * r + 1], targets[5 * r + 2], targets[5 * r + 3],
                   in_, un);
            loss += 1.0f - in_ / un;
        }
    }

    // warp reduce (f32)
#pragma unroll
    for (int off = 16; off > 0; off >>= 1)
        loss += __shfl_down_sync(0xFFFFFFFFu, loss, off);

    __shared__ double wsum[THREADS / 32];
    __shared__ bool is_last;
    int lane = threadIdx.x & 31;
    int wid = threadIdx.x >> 5;
    if (lane == 0) wsum[wid] = (double)loss;
    __syncthreads();

    if (threadIdx.x == 0) {
        double s = 0.0;
#pragma unroll
        for (int w = 0; w < THREADS / 32; w++) s += wsum[w];
        atomicAdd(&g_acc, s);
        __threadfence();
        unsigned int ticket = atomicAdd(&g_count, 1u);
        is_last = (ticket == gridDim.x - 1);
    }
    __syncthreads();

    if (is_last && threadIdx.x == 0) {
        double acc = atomicAdd(&g_acc, 0.0);   // L2-coherent read
        out[0] = (float)(acc / (double)n_rows);
        atomicExch(reinterpret_cast<unsigned long long*>(&g_acc), 0ull);
        atomicExch(&g_count, 0u);
    }
}

extern "C" void kernel_launch(void* const* d_in, const int* in_sizes, int n_in,
                              void* d_out, int out_size) {
    const float* preds = (const float*)d_in[0];
    const float* targets = (const float*)d_in[1];
    int n_rows = in_sizes[0] / 5;
    int n_groups = n_rows / 4;

    int n_tiles = (n_groups + TILE_G - 1) / TILE_G;
    // Persistent single-wave grid: 148 SMs x 5 CTAs (smem-limited: 2x21KB/CTA).
    int blocks = 148 * 5;
    if (n_tiles < blocks) blocks = n_tiles > 0 ? n_tiles : 1;

    k_main<<<blocks, THREADS>>>(preds, targets, n_groups, n_rows, (float*)d_out);
}

// round 7
// speedup vs baseline: 1.1308x; 1.1308x over previous
#include <cuda_runtime.h>
#include <cuda_bf16.h>

// ---------------------------------------------------------------------------
// SphericalIoULoss: mean(1 - sph_iou(preds, targets)), N rows of 5 f32.
// Math: area = 4*asin(sin(a/2)sin(b/2)) (exact transform of the reference's
// 4*acos(-s)-2pi); bounded args -> FMA-only polynomials (rel_err 1.2e-7
// validated); 1 RCP per 4 rows via grouped inversion.
//
// Memory: WARP-PRIVATE smem transpose. Each warp stages 32 groups (2560B per
// tensor) with 5 coalesced LDG.128 per tensor (4 L1 wavefronts each, vs 20
// for 80B-strided direct loads), scatters into a pad-21 layout, syncwarp,
// then reads stride-21 (conflict-free, gcd(21,32)=1). No __syncthreads in
// the main loop -> warps pipeline independently, DRAM latency overlapped.
// ---------------------------------------------------------------------------

#define THREADS   256
#define WARPS     (THREADS / 32)
#define PAD       21                 // floats per group in smem
#define WTILE     (32 * PAD)         // 672 floats per warp buffer

__device__ double g_acc = 0.0;
__device__ unsigned int g_count = 0;

// sin(x), x in [0, ~0.55]
__device__ __forceinline__ float sin_s(float x) {
    float x2 = x * x;
    float t = fmaf(x2, -1.98412698e-4f, 8.33333333e-3f);
    t = fmaf(x2, t, -1.66666667e-1f);
    t = fmaf(x2, t, 1.0f);
    return x * t;
}
// asin(x), x in [0, ~0.27]
__device__ __forceinline__ float asin_s(float x) {
    float x2 = x * x;
    float t = fmaf(x2, 4.46428571e-2f, 7.50000000e-2f);
    t = fmaf(x2, t, 1.66666667e-1f);
    t = fmaf(x2, t, 1.0f);
    return x * t;
}
// cos(x), |x| <= pi/2
__device__ __forceinline__ float cos_m(float x) {
    float x2 = x * x;
    float t = fmaf(x2, -2.75573192e-7f, 2.48015873e-5f);
    t = fmaf(x2, t, -1.38888889e-3f);
    t = fmaf(x2, t, 4.16666667e-2f);
    t = fmaf(x2, t, -0.5f);
    t = fmaf(x2, t, 1.0f);
    return t;
}

__device__ __forceinline__ void row_iu(float t1, float p1, float a1, float b1,
                                       float t2, float p2, float a2, float b2,
                                       float& inter, float& uni) {
    float ha1 = 0.5f * a1, hb1 = 0.5f * b1;
    float ha2 = 0.5f * a2, hb2 = 0.5f * b2;
    float area1 = 4.0f * asin_s(sin_s(ha1) * sin_s(hb1));
    float area2 = 4.0f * asin_s(sin_s(ha2) * sin_s(hb2));
    float dfx = (t2 - t1) * cos_m(0.5f * (p1 + p2));
    float dfy = p2 - p1;
    float iw = fminf(ha1, dfx + ha2) - fmaxf(-ha1, dfx - ha2);
    iw = fmaxf(iw, 0.0f);
    float ih = fminf(hb1, dfy + hb2) - fmaxf(-hb1, dfy - hb2);
    ih = fmaxf(ih, 0.0f);
    inter = 4.0f * asin_s(sin_s(0.5f * iw) * sin_s(0.5f * ih));
    uni = fmaxf(area1 + area2 - inter, 1e-8f);
}

// Scatter float4 #i (i in [0,160), warp-tile-local) into pad-21 smem.
// f = 4i; g = f/20; j = f%20 (j multiple of 4, <=16: never crosses a group).
__device__ __forceinline__ void scatter4(float* __restrict__ sm, int i, float4 v) {
    int f = i * 4;
    int g = f / 20;
    int j = f - g * 20;
    float* p = sm + g * PAD + j;
    p[0] = v.x; p[1] = v.y; p[2] = v.z; p[3] = v.w;
}

// Direct-load fallback for tail groups (same math, strided loads).
__device__ __forceinline__ float group4_direct(const float* __restrict__ preds,
                                               const float* __restrict__ targets,
                                               long g) {
    const float4* p4 = reinterpret_cast<const float4*>(preds) + g * 5;
    const float4* q4 = reinterpret_cast<const float4*>(targets) + g * 5;
    float pv[20], qv[20];
#pragma unroll
    for (int k = 0; k < 5; k++) {
        float4 v = p4[k];
        pv[4 * k] = v.x; pv[4 * k + 1] = v.y; pv[4 * k + 2] = v.z; pv[4 * k + 3] = v.w;
        float4 w = q4[k];
        qv[4 * k] = w.x; qv[4 * k + 1] = w.y; qv[4 * k + 2] = w.z; qv[4 * k + 3] = w.w;
    }
    float s = 0.0f;
#pragma unroll
    for (int r = 0; r < 4; r++) {
        float in_, un;
        row_iu(pv[5 * r], pv[5 * r + 1], pv[5 * r + 2], pv[5 * r + 3],
               qv[5 * r], qv[5 * r + 1], qv[5 * r + 2], qv[5 * r + 3], in_, un);
        s += 1.0f - in_ / un;
    }
    return s;
}

__global__ __launch_bounds__(THREADS)
void k_main(const float* __restrict__ preds,
            const float* __restrict__ targets,
            int n_groups,
            int n_rows,
            float* __restrict__ out) {
    __shared__ float smP[WARPS][WTILE];
    __shared__ float smQ[WARPS][WTILE];

    int lane = threadIdx.x & 31;
    int wid = threadIdx.x >> 5;
    float* sP = smP[wid];
    float* sQ = smQ[wid];

    int n_tiles = n_groups >> 5;                 // warp-tiles of 32 groups
    long gw = (long)blockIdx.x * WARPS + wid;    // global warp id
    long wstride = (long)gridDim.x * WARPS;

    float loss = 0.0f;

    for (long t = gw; t < n_tiles; t += wstride) {
        long F = t * 160;                         // first float4 of this tile
        const float4* P = reinterpret_cast<const float4*>(preds) + F;
        const float4* Q = reinterpret_cast<const float4*>(targets) + F;

        // Coalesced loads: warp covers 160 float4 per tensor (512B per LDG).
        float4 vp[5], vq[5];
#pragma unroll
        for (int k = 0; k < 5; k++) vp[k] = P[32 * k + lane];
#pragma unroll
        for (int k = 0; k < 5; k++) vq[k] = Q[32 * k + lane];

        __syncwarp();                             // prior reads done before overwrite
#pragma unroll
        for (int k = 0; k < 5; k++) scatter4(sP, 32 * k + lane, vp[k]);
#pragma unroll
        for (int k = 0; k < 5; k++) scatter4(sQ, 32 * k + lane, vq[k]);
        __syncwarp();

        // Compute: lane owns group 'lane' of this tile; stride-21 reads are
        // bank-conflict-free.
        const float* pv = sP + lane * PAD;
        const float* qv = sQ + lane * PAD;
        float inter[4], uni[4];
#pragma unroll
        for (int r = 0; r < 4; r++) {
            row_iu(pv[5 * r], pv[5 * r + 1], pv[5 * r + 2], pv[5 * r + 3],
                   qv[5 * r], qv[5 * r + 1], qv[5 * r + 2], qv[5 * r + 3],
                   inter[r], uni[r]);
        }
        float u01 = uni[0] * uni[1];
        float u23 = uni[2] * uni[3];
        float r_all = 1.0f / (u01 * u23);
        float r01 = r_all * u23;
        float r23 = r_all * u01;
        loss += 4.0f - (inter[0] * (r01 * uni[1]) + inter[1] * (r01 * uni[0]) +
                        inter[2] * (r23 * uni[3]) + inter[3] * (r23 * uni[2]));
    }

    // Tail groups not covered by full warp-tiles (block 0, warp 0).
    long full_g = (long)n_tiles * 32;
    if (blockIdx.x == 0 && wid == 0) {
        long g = full_g + lane;
        if (g < n_groups) loss += group4_direct(preds, targets, g);
    }
    // Tail rows beyond full groups (none when n_rows % 4 == 0).
    if (blockIdx.x == 0 && threadIdx.x == 0) {
        for (long r = (long)n_groups * 4; r < (long)n_rows; r++) {
            float in_, un;
            row_iu(preds[5 * r], preds[5 * r + 1], preds[5 * r + 2], preds[5 * r + 3],
                   targets[5 * r], targets[5 * r + 1], targets[5 * r + 2], targets[5 * r + 3],
                   in_, un);
            loss += 1.0f - in_ / un;
        }
    }

    // Reduction: warp shfl -> block doubles -> one atomic per block.
#pragma unroll
    for (int off = 16; off > 0; off >>= 1)
        loss += __shfl_down_sync(0xFFFFFFFFu, loss, off);

    __shared__ double wsum[WARPS];
    __shared__ bool is_last;
    if (lane == 0) wsum[wid] = (double)loss;
    __syncthreads();

    if (threadIdx.x == 0) {
        double s = 0.0;
#pragma unroll
        for (int w = 0; w < WARPS; w++) s += wsum[w];
        atomicAdd(&g_acc, s);
        __threadfence();
        unsigned int ticket = atomicAdd(&g_count, 1u);
        is_last = (ticket == gridDim.x - 1);
    }
    __syncthreads();

    if (is_last && threadIdx.x == 0) {
        double acc = atomicAdd(&g_acc, 0.0);      // L2-coherent read
        out[0] = (float)(acc / (double)n_rows);
        atomicExch(reinterpret_cast<unsigned long long*>(&g_acc), 0ull);
        atomicExch(&g_count, 0u);
    }
}

extern "C" void kernel_launch(void* const* d_in, const int* in_sizes, int n_in,
                              void* d_out, int out_size) {
    const float* preds = (const float*)d_in[0];
    const float* targets = (const float*)d_in[1];
    int n_rows = in_sizes[0] / 5;
    int n_groups = n_rows / 4;

    // One resident wave: 148 SMs x 5 CTAs (smem-limited: ~42KB/CTA).
    int blocks = 148 * 5;
    long warp_tiles = n_groups >> 5;
    long max_blocks = (warp_tiles + WARPS - 1) / WARPS;
    if (max_blocks < 1) max_blocks = 1;
    if (max_blocks < blocks) blocks = (int)max_blocks;

    k_main<<<blocks, THREADS>>>(preds, targets, n_groups, n_rows, (float*)d_out);
}

// round 9
// speedup vs baseline: 1.3169x; 1.1645x over previous
#include <cuda_runtime.h>
#include <cuda_bf16.h>

// ---------------------------------------------------------------------------
// SphericalIoULoss: mean(1 - sph_iou(preds, targets)), N rows of 5 f32.
// Math: area = 4*asin(sin(a/2)sin(b/2)) (exact transform of the reference's
// 4*acos(-s)-2pi); bounded args -> FMA-only polynomials (validated
// rel_err=1.2e-7); 1 RCP per 4 rows via grouped inversion.
//
// Register double-buffered PREFETCH. Each thread processes groups of 4 rows
// (5 float4 per tensor) with stride = total threads; the next group's 10
// float4 loads are issued before computing the current group, so every warp
// keeps ~1280B outstanding ~continuously. 16 warps/SM x 1280B ~= 20.5KB in
// flight per SM > ~15KB needed to saturate HBM. No smem in the main loop.
// __launch_bounds__(256,2) caps regs at 128 (no spills).
// ---------------------------------------------------------------------------

#define THREADS 256

__device__ double g_acc = 0.0;
__device__ unsigned int g_count = 0;

// sin(x), x in [0, ~0.55]
__device__ __forceinline__ float sin_s(float x) {
    float x2 = x * x;
    float t = fmaf(x2, -1.98412698e-4f, 8.33333333e-3f);
    t = fmaf(x2, t, -1.66666667e-1f);
    t = fmaf(x2, t, 1.0f);
    return x * t;
}
// asin(x), x in [0, ~0.27]
__device__ __forceinline__ float asin_s(float x) {
    float x2 = x * x;
    float t = fmaf(x2, 4.46428571e-2f, 7.50000000e-2f);
    t = fmaf(x2, t, 1.66666667e-1f);
    t = fmaf(x2, t, 1.0f);
    return x * t;
}
// cos(x), |x| <= pi/2
__device__ __forceinline__ float cos_m(float x) {
    float x2 = x * x;
    float t = fmaf(x2, -2.75573192e-7f, 2.48015873e-5f);
    t = fmaf(x2, t, -1.38888889e-3f);
    t = fmaf(x2, t, 4.16666667e-2f);
    t = fmaf(x2, t, -0.5f);
    t = fmaf(x2, t, 1.0f);
    return t;
}

__device__ __forceinline__ void row_iu(float t1, float p1, float a1, float b1,
                                       float t2, float p2, float a2, float b2,
                                       float& inter, float& uni) {
    float ha1 = 0.5f * a1, hb1 = 0.5f * b1;
    float ha2 = 0.5f * a2, hb2 = 0.5f * b2;
    float area1 = 4.0f * asin_s(sin_s(ha1) * sin_s(hb1));
    float area2 = 4.0f * asin_s(sin_s(ha2) * sin_s(hb2));
    float dfx = (t2 - t1) * cos_m(0.5f * (p1 + p2));
    float dfy = p2 - p1;
    float iw = fminf(ha1, dfx + ha2) - fmaxf(-ha1, dfx - ha2);
    iw = fmaxf(iw, 0.0f);
    float ih = fminf(hb1, dfy + hb2) - fmaxf(-hb1, dfy - hb2);
    ih = fmaxf(ih, 0.0f);
    inter = 4.0f * asin_s(sin_s(0.5f * iw) * sin_s(0.5f * ih));
    uni = fmaxf(area1 + area2 - inter, 1e-8f);
}

// Load one group's 10 float4 (5 preds + 5 targets).
__device__ __forceinline__ void load_g(const float4* __restrict__ P,
                                       const float4* __restrict__ Q,
                                       long g, float4* vp, float4* vq) {
    const float4* p = P + g * 5;
    const float4* q = Q + g * 5;
#pragma unroll
    for (int k = 0; k < 5; k++) vp[k] = p[k];
#pragma unroll
    for (int k = 0; k < 5; k++) vq[k] = q[k];
}

// Compute loss contribution of one group from its 10 float4.
__device__ __forceinline__ float comp_g(const float4* vp, const float4* vq) {
    float pv[20], qv[20];
#pragma unroll
    for (int k = 0; k < 5; k++) {
        pv[4 * k] = vp[k].x; pv[4 * k + 1] = vp[k].y;
        pv[4 * k + 2] = vp[k].z; pv[4 * k + 3] = vp[k].w;
        qv[4 * k] = vq[k].x; qv[4 * k + 1] = vq[k].y;
        qv[4 * k + 2] = vq[k].z; qv[4 * k + 3] = vq[k].w;
    }
    float inter[4], uni[4];
#pragma unroll
    for (int r = 0; r < 4; r++) {
        row_iu(pv[5 * r], pv[5 * r + 1], pv[5 * r + 2], pv[5 * r + 3],
               qv[5 * r], qv[5 * r + 1], qv[5 * r + 2], qv[5 * r + 3],
               inter[r], uni[r]);
    }
    float u01 = uni[0] * uni[1];
    float u23 = uni[2] * uni[3];
    float r_all = 1.0f / (u01 * u23);
    float r01 = r_all * u23;
    float r23 = r_all * u01;
    return 4.0f - (inter[0] * (r01 * uni[1]) + inter[1] * (r01 * uni[0]) +
                   inter[2] * (r23 * uni[3]) + inter[3] * (r23 * uni[2]));
}

__global__ __launch_bounds__(THREADS, 2)
void k_main(const float* __restrict__ preds,
            const float* __restrict__ targets,
            int n_groups,
            int n_rows,
            float* __restrict__ out) {
    const float4* P = reinterpret_cast<const float4*>(preds);
    const float4* Q = reinterpret_cast<const float4*>(targets);

    long tid = (long)blockIdx.x * THREADS + threadIdx.x;
    long T = (long)gridDim.x * THREADS;

    float loss = 0.0f;
    float4 pA[5], qA[5], pB[5], qB[5];

    long g = tid;
    bool validA = g < n_groups;
    if (validA) load_g(P, Q, g, pA, qA);

    while (validA) {
        // Prefetch next into B, compute A.
        long gn = g + T;
        bool validB = gn < n_groups;
        if (validB) load_g(P, Q, gn, pB, qB);
        loss += comp_g(pA, qA);
        g = gn;
        if (!validB) break;

        // Prefetch next into A, compute B.
        gn = g + T;
        bool validA2 = gn < n_groups;
        if (validA2) load_g(P, Q, gn, pA, qA);
        loss += comp_g(pB, qB);
        g = gn;
        validA = validA2;
    }

    // Tail rows beyond full groups (none when n_rows % 4 == 0).
    if (blockIdx.x == 0 && threadIdx.x == 0) {
        for (long r = (long)n_groups * 4; r < (long)n_rows; r++) {
            float in_, un;
            row_iu(preds[5 * r], preds[5 * r + 1], preds[5 * r + 2], preds[5 * r + 3],
                   targets[5 * r], targets[5 * r + 1], targets[5 * r + 2], targets[5 * r + 3],
                   in_, un);
            loss += 1.0f - in_ / un;
        }
    }

    // Reduction: warp shfl -> block doubles -> one atomic per block.
#pragma unroll
    for (int off = 16; off > 0; off >>= 1)
        loss += __shfl_down_sync(0xFFFFFFFFu, loss, off);

    __shared__ double wsum[THREADS / 32];
    __shared__ bool is_last;
    int lane = threadIdx.x & 31;
    int wid = threadIdx.x >> 5;
    if (lane == 0) wsum[wid] = (double)loss;
    __syncthreads();

    if (threadIdx.x == 0) {
        double s = 0.0;
#pragma unroll
        for (int w = 0; w < THREADS / 32; w++) s += wsum[w];
        atomicAdd(&g_acc, s);
        __threadfence();
        unsigned int ticket = atomicAdd(&g_count, 1u);
        is_last = (ticket == gridDim.x - 1);
    }
    __syncthreads();

    if (is_last && threadIdx.x == 0) {
        double acc = atomicAdd(&g_acc, 0.0);   // L2-coherent read
        out[0] = (float)(acc / (double)n_rows);
        atomicExch(reinterpret_cast<unsigned long long*>(&g_acc), 0ull);
        atomicExch(&g_count, 0u);
    }
}

extern "C" void kernel_launch(void* const* d_in, const int* in_sizes, int n_in,
                              void* d_out, int out_size) {
    const float* preds = (const float*)d_in[0];
    const float* targets = (const float*)d_in[1];
    int n_rows = in_sizes[0] / 5;
    int n_groups = n_rows / 4;

    // 2 CTAs/SM (reg-limited via __launch_bounds__(256,2)): single wave.
    int blocks = 148 * 2;
    long max_needed = ((long)n_groups + THREADS - 1) / THREADS;
    if (max_needed < 1) max_needed = 1;
    if (max_needed < blocks) blocks = (int)max_needed;

    k_main<<<blocks, THREADS>>>(preds, targets, n_groups, n_rows, (float*)d_out);
}